// round 16
// baseline (speedup 1.0000x reference)
#include <cuda_runtime.h>
#include <cuda_fp16.h>
#include <math_constants.h>
#include <cstdint>

#define DIM 128
#define KCODES 2048
#define NROWS 65536
#define NZ (NROWS * DIM)
#define TILE_M 128
#define CHUNK 64
#define CHUNKS 32
#define NTH 256

__device__ __align__(16) float g_t[KCODES];
__device__ int   g_idx[NROWS];
__device__ float g_part[1024];
__device__ __align__(16) __half g_bh[KCODES * DIM];   // fl16(2048*e)
__device__ __align__(16) float g_et[DIM * KCODES];    // k-major transposed emb (1 MB)
__device__ int g_cnt;
__device__ int g_list[NROWS];

// ---- smem byte offsets (stage 1): ~106 KB -> 2 CTAs/SM ----
#define OFF_A    0
#define OFF_B    32768
#define BUFSZ    16384
#define OFF_TALL 98304
#define OFF_SROW 106496
#define OFF_BEST 107008
#define OFF_IDX  107520
#define OFF_B2   108032
#define SMEM_SZ  108544

// ---- PTX helpers ----
static __device__ __forceinline__ void ldsm4(uint32_t* r, uint32_t a) {
    asm volatile("ldmatrix.sync.aligned.m8n8.x4.shared.b16 {%0,%1,%2,%3}, [%4];"
                 : "=r"(r[0]), "=r"(r[1]), "=r"(r[2]), "=r"(r[3]) : "r"(a));
}
static __device__ __forceinline__ void mma16816(float* c, const uint32_t* a,
                                                uint32_t b0, uint32_t b1) {
    asm volatile("mma.sync.aligned.m16n8k16.row.col.f32.f16.f16.f32 "
                 "{%0,%1,%2,%3}, {%4,%5,%6,%7}, {%8,%9}, {%0,%1,%2,%3};"
                 : "+f"(c[0]), "+f"(c[1]), "+f"(c[2]), "+f"(c[3])
                 : "r"(a[0]), "r"(a[1]), "r"(a[2]), "r"(a[3]), "r"(b0), "r"(b1));
}
#define CP_ASYNC16(d, s) asm volatile("cp.async.ca.shared.global [%0], [%1], 16;" :: "r"(d), "l"(s))
#define CP_COMMIT() asm volatile("cp.async.commit_group;" ::: "memory")
#define CP_WAIT0()  asm volatile("cp.async.wait_group 0;" ::: "memory")
#define CP_WAIT1()  asm volatile("cp.async.wait_group 1;" ::: "memory")
#define CP_WAIT2()  asm volatile("cp.async.wait_group 2;" ::: "memory")

// ---- f32x2 helpers ----
#define FMA2(d, a, b) asm("fma.rn.f32x2 %0, %1, %2, %0;" : "+l"(d) : "l"(a), "l"(b))
static __device__ __forceinline__ unsigned long long pack2(float x) {
    unsigned long long r;
    unsigned int u = __float_as_uint(x);
    asm("mov.b64 %0, {%1, %1};" : "=l"(r) : "r"(u));
    return r;
}
static __device__ __forceinline__ void unpack2(unsigned long long v, float& lo, float& hi) {
    unsigned int a, b;
    asm("mov.b64 {%0, %1}, %2;" : "=r"(a), "=r"(b) : "l"(v));
    lo = __uint_as_float(a);
    hi = __uint_as_float(b);
}

// ---- prep: ||e||^2, exact sequential fp32, coalesced; zero counter ----
__global__ __launch_bounds__(128)
void k_embnorm(const float* __restrict__ emb) {
    __shared__ float sm[128 * 33];
    const int tid = threadIdx.x;
    const int cb = blockIdx.x * 128;
    if (blockIdx.x == 0 && tid == 0) g_cnt = 0;
    float s = 0.f;
    for (int kc = 0; kc < 4; ++kc) {
        __syncthreads();
        for (int i = tid; i < 128 * 32; i += 128) {
            int cl = i >> 5, kk = i & 31;
            sm[cl * 33 + kk] = emb[(size_t)(cb + cl) * DIM + kc * 32 + kk];
        }
        __syncthreads();
        #pragma unroll 8
        for (int kk = 0; kk < 32; ++kk) {
            float v = sm[tid * 33 + kk];
            s = __fadd_rn(s, __fmul_rn(v, v));
        }
    }
    g_t[cb + tid] = s;
}

// ---- prep: f16 codebook scaled by 2048 ----
__global__ void k_split(const float* __restrict__ emb) {
    int idx = blockIdx.x * blockDim.x + threadIdx.x;
    g_bh[idx] = __float2half_rn(__fmul_rn(emb[idx], 2048.0f));
}

// ---- prep: transpose emb -> g_et[k][2048] (smem 32x32 tiles) ----
__global__ __launch_bounds__(256)
void k_transpose(const float* __restrict__ emb) {
    __shared__ float t[32][33];
    const int bx = blockIdx.x;            // 64 tiles along codes
    const int by = blockIdx.y;            // 4 tiles along k
    const int tx = threadIdx.x & 31, ty = threadIdx.x >> 5;  // 32 x 8
    const int c0 = bx * 32, k0 = by * 32;
    #pragma unroll
    for (int j = 0; j < 4; ++j) {
        int c = ty + j * 8;
        t[c][tx] = emb[(size_t)(c0 + c) * DIM + k0 + tx];   // coalesced in k
    }
    __syncthreads();
    #pragma unroll
    for (int j = 0; j < 4; ++j) {
        int k = ty + j * 8;
        g_et[(size_t)(k0 + k) * KCODES + c0 + tx] = t[tx][k];  // coalesced in c
    }
}

// ---- B-chunk async fill (stage 1) ----
static __device__ __forceinline__ void fill_async(uint32_t bBase, int chunk, int tid) {
    const char* src = (const char*)g_bh + (size_t)chunk * CHUNK * 256;
    #pragma unroll
    for (int j = 0; j < 4; ++j) {
        int i = tid + j * NTH;
        int code = i >> 4;
        int kg = i & 15;
        uint32_t d = bBase + (uint32_t)(code * 256 + (((kg & ~7) | ((kg ^ code) & 7)) << 4));
        CP_ASYNC16(d, src + code * 256 + kg * 16);
    }
    CP_COMMIT();
}

// ---- stage 1: pure-f16 HMMA GEMM (K=128) + argmin + top-2 margin flag ----
__global__ __launch_bounds__(NTH, 2)
void k_argmin_tc(const float* __restrict__ z) {
    extern __shared__ char smc[];
    uint32_t sb;
    asm("{ .reg .u64 t; cvta.to.shared.u64 t, %1; cvt.u32.u64 %0, t; }" : "=r"(sb) : "l"(smc));
    float* tall  = (float*)(smc + OFF_TALL);
    float* srow  = (float*)(smc + OFF_SROW);
    float* bestA = (float*)(smc + OFF_BEST);
    int*   idxA  = (int*)(smc + OFF_IDX);
    float* b2A   = (float*)(smc + OFF_B2);

    const int tid = threadIdx.x;
    const int lane = tid & 31, wid = tid >> 5;
    const int wm = wid & 3, wn = wid >> 2;
    const int rbase = blockIdx.x * TILE_M;

    fill_async(sb + OFF_B + 0 * BUFSZ, 0, tid);
    fill_async(sb + OFF_B + 1 * BUFSZ, 1, tid);
    fill_async(sb + OFF_B + 2 * BUFSZ, 2, tid);

    for (int i = tid; i < KCODES / 4; i += NTH)
        ((float4*)tall)[i] = ((const float4*)g_t)[i];

    {
        int r = tid >> 1, half = tid & 1;
        const float* zr = z + (size_t)(rbase + r) * DIM + half * 64;
        char* arow = smc + OFF_A + r * 256;
        int rx = r & 7;
        #pragma unroll
        for (int g = 0; g < 8; ++g) {
            float4 v0 = *(const float4*)(zr + g * 8);
            float4 v1 = *(const float4*)(zr + g * 8 + 4);
            float f[8] = {v0.x, v0.y, v0.z, v0.w, v1.x, v1.y, v1.z, v1.w};
            uint32_t hp[4];
            #pragma unroll
            for (int e = 0; e < 4; ++e) {
                __half a = __float2half_rn(f[2 * e]);
                __half b = __float2half_rn(f[2 * e + 1]);
                hp[e] = (uint32_t)__half_as_ushort(a) | ((uint32_t)__half_as_ushort(b) << 16);
            }
            int kg0 = half * 8 + g;
            int ks0 = (kg0 & ~7) | ((kg0 & 7) ^ rx);
            *(uint4*)(arow + ks0 * 16) = *(uint4*)hp;
        }
    }

    if (tid < TILE_M) {
        const float* zr = z + (size_t)(rbase + tid) * DIM;
        float s = 0.f;
        #pragma unroll 8
        for (int k = 0; k < DIM; ++k)
            s = __fadd_rn(s, __fmul_rn(zr[k], zr[k]));
        srow[tid] = s;
    }
    __syncthreads();

    const int rx7 = lane & 7;
    const int klane = (lane >> 4) & 1;
    const uint32_t aRow0 = sb + OFF_A +
        (uint32_t)((wm * 32 + (lane & 7) + ((lane & 8) ? 8 : 0)) * 256);
    const uint32_t bRowOff =
        (uint32_t)((wn * 32 + (lane & 7) + ((lane & 8) ? 8 : 0)) * 256);

    float s_r[4]; int rowid[4];
    #pragma unroll
    for (int mi = 0; mi < 2; ++mi)
        #pragma unroll
        for (int h = 0; h < 2; ++h) {
            int rr = wm * 32 + mi * 16 + (lane >> 2) + 8 * h;
            rowid[mi * 2 + h] = rr;
            s_r[mi * 2 + h] = srow[rr];
        }
    float best[4], bsec[4]; int bidx[4];
    #pragma unroll
    for (int s = 0; s < 4; ++s) { best[s] = CUDART_INF_F; bsec[s] = CUDART_INF_F; bidx[s] = 0; }

    for (int c = 0; c < CHUNKS; ++c) {
        if (c < CHUNKS - 2) CP_WAIT2(); else if (c == CHUNKS - 2) CP_WAIT1(); else CP_WAIT0();
        __syncthreads();
        if (c + 3 < CHUNKS)
            fill_async(sb + OFF_B + ((c + 3) & 3) * BUFSZ, c + 3, tid);
        const uint32_t bBase = sb + OFF_B + (c & 3) * BUFSZ;

        float acc[2][4][4];
        #pragma unroll
        for (int i = 0; i < 32; ++i) ((float*)acc)[i] = 0.f;

        #pragma unroll
        for (int ks = 0; ks < 8; ++ks) {
            const int C = ks * 2 + klane;
            const uint32_t slot = (uint32_t)(((C & ~7) | ((C & 7) ^ rx7)) << 4);
            uint32_t A0[4], A1[4], B0[4], B1[4];
            ldsm4(A0, aRow0 + slot);
            ldsm4(A1, aRow0 + 16 * 256 + slot);
            ldsm4(B0, bBase + bRowOff + slot);
            ldsm4(B1, bBase + bRowOff + 16 * 256 + slot);
            mma16816(acc[0][0], A0, B0[0], B0[2]);
            mma16816(acc[0][1], A0, B0[1], B0[3]);
            mma16816(acc[0][2], A0, B1[0], B1[2]);
            mma16816(acc[0][3], A0, B1[1], B1[3]);
            mma16816(acc[1][0], A1, B0[0], B0[2]);
            mma16816(acc[1][1], A1, B0[1], B0[3]);
            mma16816(acc[1][2], A1, B1[0], B1[2]);
            mma16816(acc[1][3], A1, B1[1], B1[3]);
        }

        const int cb0 = c * CHUNK + wn * 32 + 2 * (lane & 3);
        #pragma unroll
        for (int mi = 0; mi < 2; ++mi)
            #pragma unroll
            for (int ni = 0; ni < 4; ++ni) {
                const float* cc = acc[mi][ni];
                int code = cb0 + ni * 8;
                float t0 = tall[code], t1 = tall[code + 1];
                #pragma unroll
                for (int h = 0; h < 2; ++h) {
                    int s = mi * 2 + h;
                    float d0 = __fadd_rn(__fsub_rn(s_r[s], __fmul_rn(cc[2 * h],     9.765625e-4f)), t0);
                    float d1 = __fadd_rn(__fsub_rn(s_r[s], __fmul_rn(cc[2 * h + 1], 9.765625e-4f)), t1);
                    if (d0 < best[s]) { bsec[s] = best[s]; best[s] = d0; bidx[s] = code; }
                    else if (d0 < bsec[s]) bsec[s] = d0;
                    if (d1 < best[s]) { bsec[s] = best[s]; best[s] = d1; bidx[s] = code + 1; }
                    else if (d1 < bsec[s]) bsec[s] = d1;
                }
            }
    }

    #pragma unroll
    for (int s = 0; s < 4; ++s) {
        float v = best[s], v2 = bsec[s]; int ix = bidx[s];
        #pragma unroll
        for (int off = 2; off > 0; off >>= 1) {
            float o1 = __shfl_down_sync(0xffffffffu, v, off, 4);
            int   oi = __shfl_down_sync(0xffffffffu, ix, off, 4);
            float o2 = __shfl_down_sync(0xffffffffu, v2, off, 4);
            if (o1 < v || (o1 == v && oi < ix)) { v2 = fminf(v, o2); v = o1; ix = oi; }
            else { v2 = fminf(v2, o1); }
        }
        best[s] = v; bsec[s] = v2; bidx[s] = ix;
    }
    if (wn == 0 && (lane & 3) == 0) {
        #pragma unroll
        for (int s = 0; s < 4; ++s) {
            bestA[rowid[s]] = best[s]; idxA[rowid[s]] = bidx[s]; b2A[rowid[s]] = bsec[s];
        }
    }
    __syncthreads();
    if (wn == 1 && (lane & 3) == 0) {
        #pragma unroll
        for (int s = 0; s < 4; ++s) {
            float a1 = bestA[rowid[s]], a2 = b2A[rowid[s]]; int ai = idxA[rowid[s]];
            float c1 = best[s], c2 = bsec[s]; int ci = bidx[s];
            float nb1, nb2; int ni1;
            if (c1 < a1 || (c1 == a1 && ci < ai)) { nb1 = c1; ni1 = ci; nb2 = fminf(a1, c2); }
            else { nb1 = a1; ni1 = ai; nb2 = fminf(a2, c1); }
            int row = rbase + rowid[s];
            g_idx[row] = ni1;
            float margin = __fmaf_rn(nb1, 3e-7f, 3e-5f);
            if (!(nb2 - nb1 > margin)) {
                int pos = atomicAdd(&g_cnt, 1);
                g_list[pos] = row;
            }
        }
    }
}

// ---- stage 2: exact f32x2 GEMM over gathered flagged rows ----
// 32-row tiles; e chunks (64 codes x 128k fp32, 32 KB) cp.async double-buffered
// from transposed g_et. z pre-duplicated pairs in smem -> MOV-free mainloop.
#define XTM 32
#define XCH 64
#define XCHUNKS (KCODES / XCH)
__global__ __launch_bounds__(256)
void k_exact_gemm(const float* __restrict__ z) {
    extern __shared__ char smx[];
    unsigned long long* zs2 = (unsigned long long*)smx;     // [128k][32r] dup pairs  32 KB
    char*  esb  = smx + 32768;                              // 2 x 32 KB e buffers
    float* tall = (float*)(smx + 32768 + 65536);            // 2048 f32
    float* ss   = tall + KCODES;                            // 32 f32

    const int tid = threadIdx.x;
    const int cnt = g_cnt;
    if (cnt == 0) return;
    uint32_t sbx;
    asm("{ .reg .u64 t; cvta.to.shared.u64 t, %1; cvt.u32.u64 %0, t; }" : "=r"(sbx) : "l"(smx));
    const uint32_t esBase = sbx + 32768;

    for (int i = tid; i < KCODES / 4; i += 256)
        ((float4*)tall)[i] = ((const float4*)g_t)[i];

    const int tc = tid & 15;   // codes 4tc..4tc+3 of the chunk
    const int tr = tid >> 4;   // rows 2tr, 2tr+1

    for (int base = blockIdx.x * XTM; base < cnt; base += gridDim.x * XTM) {
        __syncthreads();   // previous tile fully done

        // kick off chunk 0,1 fills
        #pragma unroll
        for (int pre = 0; pre < 2; ++pre) {
            const float* src = g_et;
            #pragma unroll
            for (int j = 0; j < 8; ++j) {
                int i = tid + j * 256;        // < 2048
                int k = i >> 4, u = i & 15;
                uint32_t d = esBase + (uint32_t)(pre * 32768 + k * 256 + ((u ^ ((k >> 2) & 15)) << 4));
                CP_ASYNC16(d, src + (size_t)k * KCODES + pre * XCH + u * 4);
            }
            CP_COMMIT();
        }

        // gather z rows (tail rows clamp to duplicate), store dup pairs, k-major
        for (int i = tid; i < XTM * (DIM / 4); i += 256) {
            int r  = i & (XTM - 1);
            int k4 = i >> 5;
            int row = g_list[min(base + r, cnt - 1)];
            float4 v = *(const float4*)(z + (size_t)row * DIM + k4 * 4);
            zs2[(k4 * 4 + 0) * XTM + r] = pack2(v.x);
            zs2[(k4 * 4 + 1) * XTM + r] = pack2(v.y);
            zs2[(k4 * 4 + 2) * XTM + r] = pack2(v.z);
            zs2[(k4 * 4 + 3) * XTM + r] = pack2(v.w);
        }
        __syncthreads();

        if (tid < XTM) {
            float s = 0.f;
            #pragma unroll 8
            for (int k = 0; k < DIM; ++k) {
                float v = ((const float2*)&zs2[k * XTM + tid])->x;
                s = __fadd_rn(s, __fmul_rn(v, v));
            }
            ss[tid] = s;
        }
        __syncthreads();

        const float sr0 = ss[tr * 2];
        const float sr1 = ss[tr * 2 + 1];

        float best[2]; int bidx[2];
        best[0] = CUDART_INF_F; best[1] = CUDART_INF_F; bidx[0] = 0; bidx[1] = 0;

        for (int ch = 0; ch < XCHUNKS; ++ch) {
            if (ch < XCHUNKS - 1) CP_WAIT1(); else CP_WAIT0();
            __syncthreads();   // fill(ch) visible to all
            const uint32_t eb = esBase + (uint32_t)((ch & 1) * 32768);

            unsigned long long a00 = 0ull, a01 = 0ull, a10 = 0ull, a11 = 0ull;
            #pragma unroll 4
            for (int k = 0; k < DIM; ++k) {
                const uint32_t eoff = eb + (uint32_t)(k * 256 + ((tc ^ ((k >> 2) & 15)) << 4));
                ulonglong2 eA;
                asm volatile("ld.shared.v2.u64 {%0, %1}, [%2];"
                             : "=l"(eA.x), "=l"(eA.y) : "r"(eoff));
                ulonglong2 zp = *(const ulonglong2*)(zs2 + k * XTM + tr * 2);
                FMA2(a00, zp.x, eA.x); FMA2(a01, zp.x, eA.y);
                FMA2(a10, zp.y, eA.x); FMA2(a11, zp.y, eA.y);
            }

            // d = fl(fl(s - 2m) + t); codes ascending (4tc..4tc+3); strict <
            const int c0 = ch * XCH + tc * 4;
            float m0, m1, m2, m3, n0, n1, n2, n3;
            unpack2(a00, m0, m1); unpack2(a01, m2, m3);
            unpack2(a10, n0, n1); unpack2(a11, n2, n3);
            float t0 = tall[c0], t1 = tall[c0 + 1], t2 = tall[c0 + 2], t3 = tall[c0 + 3];
            float d;
            d = __fadd_rn(__fsub_rn(sr0, __fmul_rn(2.f, m0)), t0); if (d < best[0]) { best[0] = d; bidx[0] = c0; }
            d = __fadd_rn(__fsub_rn(sr0, __fmul_rn(2.f, m1)), t1); if (d < best[0]) { best[0] = d; bidx[0] = c0 + 1; }
            d = __fadd_rn(__fsub_rn(sr0, __fmul_rn(2.f, m2)), t2); if (d < best[0]) { best[0] = d; bidx[0] = c0 + 2; }
            d = __fadd_rn(__fsub_rn(sr0, __fmul_rn(2.f, m3)), t3); if (d < best[0]) { best[0] = d; bidx[0] = c0 + 3; }
            d = __fadd_rn(__fsub_rn(sr1, __fmul_rn(2.f, n0)), t0); if (d < best[1]) { best[1] = d; bidx[1] = c0; }
            d = __fadd_rn(__fsub_rn(sr1, __fmul_rn(2.f, n1)), t1); if (d < best[1]) { best[1] = d; bidx[1] = c0 + 1; }
            d = __fadd_rn(__fsub_rn(sr1, __fmul_rn(2.f, n2)), t2); if (d < best[1]) { best[1] = d; bidx[1] = c0 + 2; }
            d = __fadd_rn(__fsub_rn(sr1, __fmul_rn(2.f, n3)), t3); if (d < best[1]) { best[1] = d; bidx[1] = c0 + 3; }

            __syncthreads();   // all warps done reading buf[ch&1]
            if (ch + 2 < XCHUNKS) {
                const float* src = g_et;
                const int cb2 = (ch + 2) * XCH;
                #pragma unroll
                for (int j = 0; j < 8; ++j) {
                    int i = tid + j * 256;
                    int k = i >> 4, u = i & 15;
                    uint32_t dd = esBase + (uint32_t)(((ch & 1)) * 32768 + k * 256 + ((u ^ ((k >> 2) & 15)) << 4));
                    CP_ASYNC16(dd, src + (size_t)k * KCODES + cb2 + u * 4);
                }
                CP_COMMIT();
            }
        }

        // 16-lane (tc) reduce per row, tie -> lowest index
        #pragma unroll
        for (int r = 0; r < 2; ++r) {
            float v = best[r]; int ix = bidx[r];
            #pragma unroll
            for (int off = 8; off > 0; off >>= 1) {
                float v2 = __shfl_down_sync(0xffffffffu, v, off, 16);
                int   i2 = __shfl_down_sync(0xffffffffu, ix, off, 16);
                if (v2 < v || (v2 == v && i2 < ix)) { v = v2; ix = i2; }
            }
            int rl = tr * 2 + r;
            if (tc == 0 && base + rl < cnt)
                g_idx[g_list[base + rl]] = ix;
        }
    }
}

// ---- gather + straight-through + indices + loss partials ----
__global__ __launch_bounds__(256)
void k_out(const float* __restrict__ z, const float* __restrict__ emb,
           float* __restrict__ out, long long out_size) {
    __shared__ float red[256];
    const int tid = threadIdx.x;
    const long long row0 = (long long)blockIdx.x * 64;
    float lsum = 0.f;

    for (int i = tid; i < 64 * (DIM / 4); i += 256) {
        long long r  = row0 + (i >> 5);
        int       d4 = (i & 31) * 4;
        int idx = g_idx[r];
        float4 q  = *(const float4*)(emb + (size_t)idx * DIM + d4);
        long long gi = r * DIM + d4;
        float4 zz = *(const float4*)(z + gi);
        float4 o; float df;
        df = __fsub_rn(q.x, zz.x); o.x = __fadd_rn(zz.x, df); lsum += df * df;
        df = __fsub_rn(q.y, zz.y); o.y = __fadd_rn(zz.y, df); lsum += df * df;
        df = __fsub_rn(q.z, zz.z); o.z = __fadd_rn(zz.z, df); lsum += df * df;
        df = __fsub_rn(q.w, zz.w); o.w = __fadd_rn(zz.w, df); lsum += df * df;
        if (gi + 3 < out_size) *(float4*)(out + gi) = o;
    }

    if (tid < 64) {
        long long r  = row0 + tid;
        long long gi = (long long)NZ + r;
        if (gi < out_size) out[gi] = (float)g_idx[r];
    }

    red[tid] = lsum;
    __syncthreads();
    for (int s = 128; s > 0; s >>= 1) {
        if (tid < s) red[tid] += red[tid + s];
        __syncthreads();
    }
    if (tid == 0) g_part[blockIdx.x] = red[0];
}

// ---- deterministic final loss reduce ----
__global__ void k_final(float* __restrict__ out, long long out_size) {
    __shared__ float red[256];
    const int tid = threadIdx.x;
    float s = 0.f;
    for (int i = tid; i < 1024; i += 256) s += g_part[i];
    red[tid] = s;
    __syncthreads();
    for (int w = 128; w > 0; w >>= 1) {
        if (tid < w) red[tid] += red[tid + w];
        __syncthreads();
    }
    if (tid == 0) {
        float m = red[0] / (float)NZ;
        float loss = __fadd_rn(m, __fmul_rn(0.25f, m));
        long long li = (long long)NZ + NROWS;
        if (li < out_size) out[li] = loss;
    }
}

extern "C" void kernel_launch(void* const* d_in, const int* in_sizes, int n_in,
                              void* d_out, int out_size) {
    const float* z   = (const float*)d_in[0];
    const float* emb = (const float*)d_in[1];
    float* out = (float*)d_out;

    const int smem_x = 32768 + 65536 + KCODES * 4 + XTM * 4;   // ~106.2 KB
    cudaFuncSetAttribute(k_argmin_tc, cudaFuncAttributeMaxDynamicSharedMemorySize, SMEM_SZ);
    cudaFuncSetAttribute(k_exact_gemm, cudaFuncAttributeMaxDynamicSharedMemorySize, smem_x);

    k_embnorm<<<16, 128>>>(emb);
    k_split<<<(KCODES * DIM) / 256, 256>>>(emb);
    k_transpose<<<dim3(KCODES / 32, DIM / 32), 256>>>(emb);
    k_argmin_tc<<<NROWS / TILE_M, NTH, SMEM_SZ>>>(z);
    k_exact_gemm<<<296, 256, smem_x>>>(z);
    k_out<<<NROWS / 64, 256>>>(z, emb, out, (long long)out_size);
    k_final<<<1, 256>>>(out, (long long)out_size);
}

// round 17
// speedup vs baseline: 1.1249x; 1.1249x over previous
#include <cuda_runtime.h>
#include <cuda_fp16.h>
#include <math_constants.h>
#include <cstdint>

#define DIM 128
#define KCODES 2048
#define NROWS 65536
#define NZ (NROWS * DIM)
#define TILE_M 128
#define CHUNK 64
#define CHUNKS 32
#define NTH 256

__device__ __align__(16) float g_t[KCODES];
__device__ int   g_idx[NROWS];
__device__ float g_part[1024];
__device__ __align__(16) __half g_bh[KCODES * DIM];   // fl16(2048*e)
__device__ int g_cnt;
__device__ int g_list[NROWS];

// ---- smem byte offsets (stage 1): ~106 KB -> 2 CTAs/SM ----
#define OFF_A    0
#define OFF_B    32768
#define BUFSZ    16384
#define OFF_TALL 98304
#define OFF_SROW 106496
#define OFF_BEST 107008
#define OFF_IDX  107520
#define OFF_B2   108032
#define SMEM_SZ  108544

// ---- PTX helpers ----
static __device__ __forceinline__ void ldsm4(uint32_t* r, uint32_t a) {
    asm volatile("ldmatrix.sync.aligned.m8n8.x4.shared.b16 {%0,%1,%2,%3}, [%4];"
                 : "=r"(r[0]), "=r"(r[1]), "=r"(r[2]), "=r"(r[3]) : "r"(a));
}
static __device__ __forceinline__ void mma16816(float* c, const uint32_t* a,
                                                uint32_t b0, uint32_t b1) {
    asm volatile("mma.sync.aligned.m16n8k16.row.col.f32.f16.f16.f32 "
                 "{%0,%1,%2,%3}, {%4,%5,%6,%7}, {%8,%9}, {%0,%1,%2,%3};"
                 : "+f"(c[0]), "+f"(c[1]), "+f"(c[2]), "+f"(c[3])
                 : "r"(a[0]), "r"(a[1]), "r"(a[2]), "r"(a[3]), "r"(b0), "r"(b1));
}
#define CP_ASYNC16(d, s) asm volatile("cp.async.ca.shared.global [%0], [%1], 16;" :: "r"(d), "l"(s))
#define CP_COMMIT() asm volatile("cp.async.commit_group;" ::: "memory")
#define CP_WAIT0()  asm volatile("cp.async.wait_group 0;" ::: "memory")
#define CP_WAIT1()  asm volatile("cp.async.wait_group 1;" ::: "memory")
#define CP_WAIT2()  asm volatile("cp.async.wait_group 2;" ::: "memory")

// ---- f32x2 helpers for exact-GEMM fixup ----
#define FMA2(d, a, b) asm("fma.rn.f32x2 %0, %1, %2, %0;" : "+l"(d) : "l"(a), "l"(b))
static __device__ __forceinline__ unsigned long long pack2(float x) {
    unsigned long long r;
    unsigned int u = __float_as_uint(x);
    asm("mov.b64 %0, {%1, %1};" : "=l"(r) : "r"(u));
    return r;
}
static __device__ __forceinline__ void unpack2(unsigned long long v, float& lo, float& hi) {
    unsigned int a, b;
    asm("mov.b64 {%0, %1}, %2;" : "=r"(a), "=r"(b) : "l"(v));
    lo = __uint_as_float(a);
    hi = __uint_as_float(b);
}

// ---- prep: ||e||^2, exact sequential fp32, coalesced; zero counter ----
__global__ __launch_bounds__(128)
void k_embnorm(const float* __restrict__ emb) {
    __shared__ float sm[128 * 33];
    const int tid = threadIdx.x;
    const int cb = blockIdx.x * 128;
    if (blockIdx.x == 0 && tid == 0) g_cnt = 0;
    float s = 0.f;
    for (int kc = 0; kc < 4; ++kc) {
        __syncthreads();
        for (int i = tid; i < 128 * 32; i += 128) {
            int cl = i >> 5, kk = i & 31;
            sm[cl * 33 + kk] = emb[(size_t)(cb + cl) * DIM + kc * 32 + kk];
        }
        __syncthreads();
        #pragma unroll 8
        for (int kk = 0; kk < 32; ++kk) {
            float v = sm[tid * 33 + kk];
            s = __fadd_rn(s, __fmul_rn(v, v));
        }
    }
    g_t[cb + tid] = s;
}

// ---- prep: f16 codebook scaled by 2048 (exact power of 2) ----
__global__ void k_split(const float* __restrict__ emb) {
    int idx = blockIdx.x * blockDim.x + threadIdx.x;
    g_bh[idx] = __float2half_rn(__fmul_rn(emb[idx], 2048.0f));
}

// ---- B-chunk async fill ----
static __device__ __forceinline__ void fill_async(uint32_t bBase, int chunk, int tid) {
    const char* src = (const char*)g_bh + (size_t)chunk * CHUNK * 256;
    #pragma unroll
    for (int j = 0; j < 4; ++j) {
        int i = tid + j * NTH;
        int code = i >> 4;
        int kg = i & 15;
        uint32_t d = bBase + (uint32_t)(code * 256 + (((kg & ~7) | ((kg ^ code) & 7)) << 4));
        CP_ASYNC16(d, src + code * 256 + kg * 16);
    }
    CP_COMMIT();
}

// ---- stage 1: pure-f16 HMMA GEMM (K=128) + q-space argmin + top-2 margin flag ----
// q_j = t_j - acc_j/1024 ~ d_j - s (row-constant shift): same argmin, 1 FFMA per code.
__global__ __launch_bounds__(NTH, 2)
void k_argmin_tc(const float* __restrict__ z) {
    extern __shared__ char smc[];
    uint32_t sb;
    asm("{ .reg .u64 t; cvta.to.shared.u64 t, %1; cvt.u32.u64 %0, t; }" : "=r"(sb) : "l"(smc));
    float* tall  = (float*)(smc + OFF_TALL);
    float* srow  = (float*)(smc + OFF_SROW);
    float* bestA = (float*)(smc + OFF_BEST);
    int*   idxA  = (int*)(smc + OFF_IDX);
    float* b2A   = (float*)(smc + OFF_B2);

    const int tid = threadIdx.x;
    const int lane = tid & 31, wid = tid >> 5;
    const int wm = wid & 3, wn = wid >> 2;
    const int rbase = blockIdx.x * TILE_M;

    fill_async(sb + OFF_B + 0 * BUFSZ, 0, tid);
    fill_async(sb + OFF_B + 1 * BUFSZ, 1, tid);
    fill_async(sb + OFF_B + 2 * BUFSZ, 2, tid);

    for (int i = tid; i < KCODES / 4; i += NTH)
        ((float4*)tall)[i] = ((const float4*)g_t)[i];

    {
        int r = tid >> 1, half = tid & 1;
        const float* zr = z + (size_t)(rbase + r) * DIM + half * 64;
        char* arow = smc + OFF_A + r * 256;
        int rx = r & 7;
        #pragma unroll
        for (int g = 0; g < 8; ++g) {
            float4 v0 = *(const float4*)(zr + g * 8);
            float4 v1 = *(const float4*)(zr + g * 8 + 4);
            float f[8] = {v0.x, v0.y, v0.z, v0.w, v1.x, v1.y, v1.z, v1.w};
            uint32_t hp[4];
            #pragma unroll
            for (int e = 0; e < 4; ++e) {
                __half a = __float2half_rn(f[2 * e]);
                __half b = __float2half_rn(f[2 * e + 1]);
                hp[e] = (uint32_t)__half_as_ushort(a) | ((uint32_t)__half_as_ushort(b) << 16);
            }
            int kg0 = half * 8 + g;
            int ks0 = (kg0 & ~7) | ((kg0 & 7) ^ rx);
            *(uint4*)(arow + ks0 * 16) = *(uint4*)hp;
        }
    }

    if (tid < TILE_M) {
        const float* zr = z + (size_t)(rbase + tid) * DIM;
        float s = 0.f;
        #pragma unroll 8
        for (int k = 0; k < DIM; ++k)
            s = __fadd_rn(s, __fmul_rn(zr[k], zr[k]));
        srow[tid] = s;
    }
    __syncthreads();

    const int rx7 = lane & 7;
    const int klane = (lane >> 4) & 1;
    const uint32_t aRow0 = sb + OFF_A +
        (uint32_t)((wm * 32 + (lane & 7) + ((lane & 8) ? 8 : 0)) * 256);
    const uint32_t bRowOff =
        (uint32_t)((wn * 32 + (lane & 7) + ((lane & 8) ? 8 : 0)) * 256);

    float s_r[4]; int rowid[4];
    #pragma unroll
    for (int mi = 0; mi < 2; ++mi)
        #pragma unroll
        for (int h = 0; h < 2; ++h) {
            int rr = wm * 32 + mi * 16 + (lane >> 2) + 8 * h;
            rowid[mi * 2 + h] = rr;
            s_r[mi * 2 + h] = srow[rr];
        }
    float best[4], bsec[4]; int bidx[4];
    #pragma unroll
    for (int s = 0; s < 4; ++s) { best[s] = CUDART_INF_F; bsec[s] = CUDART_INF_F; bidx[s] = 0; }

    for (int c = 0; c < CHUNKS; ++c) {
        if (c < CHUNKS - 2) CP_WAIT2(); else if (c == CHUNKS - 2) CP_WAIT1(); else CP_WAIT0();
        __syncthreads();
        if (c + 3 < CHUNKS)
            fill_async(sb + OFF_B + ((c + 3) & 3) * BUFSZ, c + 3, tid);
        const uint32_t bBase = sb + OFF_B + (c & 3) * BUFSZ;

        float acc[2][4][4];
        #pragma unroll
        for (int i = 0; i < 32; ++i) ((float*)acc)[i] = 0.f;

        #pragma unroll
        for (int ks = 0; ks < 8; ++ks) {
            const int C = ks * 2 + klane;
            const uint32_t slot = (uint32_t)(((C & ~7) | ((C & 7) ^ rx7)) << 4);
            uint32_t A0[4], A1[4], B0[4], B1[4];
            ldsm4(A0, aRow0 + slot);
            ldsm4(A1, aRow0 + 16 * 256 + slot);
            ldsm4(B0, bBase + bRowOff + slot);
            ldsm4(B1, bBase + bRowOff + 16 * 256 + slot);
            mma16816(acc[0][0], A0, B0[0], B0[2]);
            mma16816(acc[0][1], A0, B0[1], B0[3]);
            mma16816(acc[0][2], A0, B1[0], B1[2]);
            mma16816(acc[0][3], A0, B1[1], B1[3]);
            mma16816(acc[1][0], A1, B0[0], B0[2]);
            mma16816(acc[1][1], A1, B0[1], B0[3]);
            mma16816(acc[1][2], A1, B1[0], B1[2]);
            mma16816(acc[1][3], A1, B1[1], B1[3]);
        }

        // q-space epilogue: q = fmaf(acc, -2^-10, t); ascending codes; strict <
        const int cb0 = c * CHUNK + wn * 32 + 2 * (lane & 3);
        #pragma unroll
        for (int mi = 0; mi < 2; ++mi)
            #pragma unroll
            for (int ni = 0; ni < 4; ++ni) {
                const float* cc = acc[mi][ni];
                int code = cb0 + ni * 8;
                float2 tp = *(const float2*)(tall + code);
                #pragma unroll
                for (int h = 0; h < 2; ++h) {
                    int s = mi * 2 + h;
                    float q0 = __fmaf_rn(cc[2 * h],     -9.765625e-4f, tp.x);
                    float q1 = __fmaf_rn(cc[2 * h + 1], -9.765625e-4f, tp.y);
                    if (q0 < best[s]) { bsec[s] = best[s]; best[s] = q0; bidx[s] = code; }
                    else if (q0 < bsec[s]) bsec[s] = q0;
                    if (q1 < best[s]) { bsec[s] = best[s]; best[s] = q1; bidx[s] = code + 1; }
                    else if (q1 < bsec[s]) bsec[s] = q1;
                }
            }
    }

    #pragma unroll
    for (int s = 0; s < 4; ++s) {
        float v = best[s], v2 = bsec[s]; int ix = bidx[s];
        #pragma unroll
        for (int off = 2; off > 0; off >>= 1) {
            float o1 = __shfl_down_sync(0xffffffffu, v, off, 4);
            int   oi = __shfl_down_sync(0xffffffffu, ix, off, 4);
            float o2 = __shfl_down_sync(0xffffffffu, v2, off, 4);
            if (o1 < v || (o1 == v && oi < ix)) { v2 = fminf(v, o2); v = o1; ix = oi; }
            else { v2 = fminf(v2, o1); }
        }
        best[s] = v; bsec[s] = v2; bidx[s] = ix;
    }
    if (wn == 0 && (lane & 3) == 0) {
        #pragma unroll
        for (int s = 0; s < 4; ++s) {
            bestA[rowid[s]] = best[s]; idxA[rowid[s]] = bidx[s]; b2A[rowid[s]] = bsec[s];
        }
    }
    __syncthreads();
    if (wn == 1 && (lane & 3) == 0) {
        #pragma unroll
        for (int s = 0; s < 4; ++s) {
            float a1 = bestA[rowid[s]], a2 = b2A[rowid[s]]; int ai = idxA[rowid[s]];
            float c1 = best[s], c2 = bsec[s]; int ci = bidx[s];
            float nb1, nb2; int ni1;
            if (c1 < a1 || (c1 == a1 && ci < ai)) { nb1 = c1; ni1 = ci; nb2 = fminf(a1, c2); }
            else { nb1 = a1; ni1 = ai; nb2 = fminf(a2, c1); }
            int row = rbase + rowid[s];
            g_idx[row] = ni1;
            // margin anchored to d-scale (s_r ~ d): covers f16 GEMM error + 2 ref-chain ulps
            float margin = __fmaf_rn(s_r[s], 3e-7f, 3e-5f);
            if (!(nb2 - nb1 > margin)) {
                int pos = atomicAdd(&g_cnt, 1);
                g_list[pos] = row;
            }
        }
    }
}

// ---- stage 2: exact f32x2-FFMA full-scan GEMM over gathered flagged rows (R15) ----
#define XTM 32
#define XTN 128
__global__ __launch_bounds__(256, 2)
void k_exact_gemm(const float* __restrict__ z, const float* __restrict__ emb) {
    extern __shared__ char smx[];
    float* zs   = (float*)smx;                    // [128k][32r]      16 KB
    float* es   = zs + DIM * XTM;                 // [128k][128c] swz 64 KB
    float* tall = es + DIM * XTN;                 // [2048]            8 KB
    float* ss   = tall + KCODES;                  // [32]

    const int tid = threadIdx.x;
    const int cnt = g_cnt;

    for (int i = tid; i < KCODES / 4; i += 256)
        ((float4*)tall)[i] = ((const float4*)g_t)[i];

    const int tc = tid & 15;
    const int tr = tid >> 4;

    for (int base = blockIdx.x * XTM; base < cnt; base += gridDim.x * XTM) {
        __syncthreads();

        for (int i = tid; i < XTM * (DIM / 4); i += 256) {
            int r  = i & (XTM - 1);
            int k4 = i >> 5;
            int row = g_list[min(base + r, cnt - 1)];
            float4 v = *(const float4*)(z + (size_t)row * DIM + k4 * 4);
            zs[(k4 * 4 + 0) * XTM + r] = v.x;
            zs[(k4 * 4 + 1) * XTM + r] = v.y;
            zs[(k4 * 4 + 2) * XTM + r] = v.z;
            zs[(k4 * 4 + 3) * XTM + r] = v.w;
        }
        __syncthreads();

        if (tid < XTM) {
            float s = 0.f;
            #pragma unroll 8
            for (int k = 0; k < DIM; ++k) {
                float v = zs[k * XTM + tid];
                s = __fadd_rn(s, __fmul_rn(v, v));
            }
            ss[tid] = s;
        }
        __syncthreads();

        float s_r[2];
        s_r[0] = ss[tr * 2];
        s_r[1] = ss[tr * 2 + 1];

        float best[2]; int bidx[2];
        best[0] = CUDART_INF_F; best[1] = CUDART_INF_F; bidx[0] = 0; bidx[1] = 0;

        for (int ch = 0; ch < KCODES / XTN; ++ch) {
            const int cbase = ch * XTN;
            __syncthreads();
            #pragma unroll
            for (int it = 0; it < XTN / 8; ++it) {
                int cl = it * 8 + (tid >> 5);
                int k4 = tid & 31;
                float4 v = *(const float4*)(emb + (size_t)(cbase + cl) * DIM + k4 * 4);
                int g = cl >> 2, off = cl & 3;
                #pragma unroll
                for (int j = 0; j < 4; ++j) {
                    int k = k4 * 4 + j;
                    es[k * XTN + (((g ^ (k >> 2)) << 2) | off)] = ((const float*)&v)[j];
                }
            }
            __syncthreads();

            unsigned long long acc[8];
            #pragma unroll
            for (int i = 0; i < 8; ++i) acc[i] = 0ull;

            #pragma unroll 4
            for (int k = 0; k < DIM; ++k) {
                const float* ek = es + k * XTN;
                const int sw = k >> 2;
                ulonglong2 eA = *(const ulonglong2*)(ek + ((tc ^ sw) << 2));
                ulonglong2 eB = *(const ulonglong2*)(ek + (((tc + 16) ^ sw) << 2));
                float2 zv = *(const float2*)(zs + k * XTM + (tr << 1));
                unsigned long long z0 = pack2(zv.x), z1 = pack2(zv.y);
                FMA2(acc[0], z0, eA.x); FMA2(acc[1], z0, eA.y);
                FMA2(acc[2], z0, eB.x); FMA2(acc[3], z0, eB.y);
                FMA2(acc[4], z1, eA.x); FMA2(acc[5], z1, eA.y);
                FMA2(acc[6], z1, eB.x); FMA2(acc[7], z1, eB.y);
            }

            #pragma unroll
            for (int r = 0; r < 2; ++r) {
                #pragma unroll
                for (int p = 0; p < 4; ++p) {
                    float mlo, mhi;
                    unpack2(acc[r * 4 + p], mlo, mhi);
                    int clocal = (p < 2) ? (tc * 4 + p * 2) : (64 + tc * 4 + (p - 2) * 2);
                    int c0 = cbase + clocal;
                    float d0 = __fadd_rn(__fsub_rn(s_r[r], __fmul_rn(2.f, mlo)), tall[c0]);
                    float d1 = __fadd_rn(__fsub_rn(s_r[r], __fmul_rn(2.f, mhi)), tall[c0 + 1]);
                    if (d0 < best[r]) { best[r] = d0; bidx[r] = c0; }
                    if (d1 < best[r]) { best[r] = d1; bidx[r] = c0 + 1; }
                }
            }
        }

        #pragma unroll
        for (int r = 0; r < 2; ++r) {
            float v = best[r]; int ix = bidx[r];
            #pragma unroll
            for (int off = 8; off > 0; off >>= 1) {
                float v2 = __shfl_down_sync(0xffffffffu, v, off, 16);
                int   i2 = __shfl_down_sync(0xffffffffu, ix, off, 16);
                if (v2 < v || (v2 == v && i2 < ix)) { v = v2; ix = i2; }
            }
            int rl = tr * 2 + r;
            if (tc == 0 && base + rl < cnt)
                g_idx[g_list[base + rl]] = ix;
        }
    }
}

// ---- gather + straight-through + indices + loss partials ----
__global__ __launch_bounds__(256)
void k_out(const float* __restrict__ z, const float* __restrict__ emb,
           float* __restrict__ out, long long out_size) {
    __shared__ float red[256];
    const int tid = threadIdx.x;
    const long long row0 = (long long)blockIdx.x * 64;
    float lsum = 0.f;

    for (int i = tid; i < 64 * (DIM / 4); i += 256) {
        long long r  = row0 + (i >> 5);
        int       d4 = (i & 31) * 4;
        int idx = g_idx[r];
        float4 q  = *(const float4*)(emb + (size_t)idx * DIM + d4);
        long long gi = r * DIM + d4;
        float4 zz = *(const float4*)(z + gi);
        float4 o; float df;
        df = __fsub_rn(q.x, zz.x); o.x = __fadd_rn(zz.x, df); lsum += df * df;
        df = __fsub_rn(q.y, zz.y); o.y = __fadd_rn(zz.y, df); lsum += df * df;
        df = __fsub_rn(q.z, zz.z); o.z = __fadd_rn(zz.z, df); lsum += df * df;
        df = __fsub_rn(q.w, zz.w); o.w = __fadd_rn(zz.w, df); lsum += df * df;
        if (gi + 3 < out_size) *(float4*)(out + gi) = o;
    }

    if (tid < 64) {
        long long r  = row0 + tid;
        long long gi = (long long)NZ + r;
        if (gi < out_size) out[gi] = (float)g_idx[r];
    }

    red[tid] = lsum;
    __syncthreads();
    for (int s = 128; s > 0; s >>= 1) {
        if (tid < s) red[tid] += red[tid + s];
        __syncthreads();
    }
    if (tid == 0) g_part[blockIdx.x] = red[0];
}

// ---- deterministic final loss reduce ----
__global__ void k_final(float* __restrict__ out, long long out_size) {
    __shared__ float red[256];
    const int tid = threadIdx.x;
    float s = 0.f;
    for (int i = tid; i < 1024; i += 256) s += g_part[i];
    red[tid] = s;
    __syncthreads();
    for (int w = 128; w > 0; w >>= 1) {
        if (tid < w) red[tid] += red[tid + w];
        __syncthreads();
    }
    if (tid == 0) {
        float m = red[0] / (float)NZ;
        float loss = __fadd_rn(m, __fmul_rn(0.25f, m));
        long long li = (long long)NZ + NROWS;
        if (li < out_size) out[li] = loss;
    }
}

extern "C" void kernel_launch(void* const* d_in, const int* in_sizes, int n_in,
                              void* d_out, int out_size) {
    const float* z   = (const float*)d_in[0];
    const float* emb = (const float*)d_in[1];
    float* out = (float*)d_out;

    const int smem_x = DIM * XTM * 4 + DIM * XTN * 4 + KCODES * 4 + XTM * 4;
    cudaFuncSetAttribute(k_argmin_tc, cudaFuncAttributeMaxDynamicSharedMemorySize, SMEM_SZ);
    cudaFuncSetAttribute(k_exact_gemm, cudaFuncAttributeMaxDynamicSharedMemorySize, smem_x);

    k_embnorm<<<16, 128>>>(emb);
    k_split<<<(KCODES * DIM) / 256, 256>>>(emb);
    k_argmin_tc<<<NROWS / TILE_M, NTH, SMEM_SZ>>>(z);
    k_exact_gemm<<<512, 256, smem_x>>>(z, emb);
    k_out<<<NROWS / 64, 256>>>(z, emb, out, (long long)out_size);
    k_final<<<1, 256>>>(out, (long long)out_size);
}